// round 13
// baseline (speedup 1.0000x reference)
#include <cuda_runtime.h>
#include <cstdint>

#define S_LEN 2048
#define HEADS 8
#define BATCH 2
#define DHEAD 128
#define BM 128
#define BN 64
#define NJT (S_LEN / BN)
#define THREADS 512

// smem: Q tf32 [128][128]*4B = 64KB; K [64 rows][512B] x2 bufs; V^T [128 rows][256B] x2
#define SM_Q 0
#define SM_K 65536   // + buf*32768
#define SM_V 131072  // + buf*32768
#define SMEM_TOTAL 196608
#define RED_STRIDE 132

#define NROWS (BATCH * HEADS * S_LEN)

__device__ uint4 g_kt[NROWS * 32];          // K as tf32, [bh*2048+j][128]
__device__ uint4 g_vt[BATCH * HEADS * 8192 * 16];  // V^T as tf32, [bh*128+d][2048]
__device__ float g_rnorm[HEADS * S_LEN];

__device__ __forceinline__ uint32_t smem_u32(const void* p) {
    uint32_t a;
    asm("{ .reg .u64 t; cvta.to.shared.u64 t, %1; cvt.u32.u64 %0, t; }" : "=r"(a) : "l"(p));
    return a;
}
__device__ __forceinline__ uint32_t f2tf(float f) {
    uint32_t r;
    asm("cvt.rna.tf32.f32 %0, %1;" : "=r"(r) : "f"(f));
    return r;
}
__device__ __forceinline__ void cpa16(uint32_t dst, const void* src) {
    asm volatile("cp.async.cg.shared.global [%0], [%1], 16;" :: "r"(dst), "l"(src));
}
__device__ __forceinline__ void ldmx4(uint32_t& r0, uint32_t& r1, uint32_t& r2, uint32_t& r3,
                                      uint32_t a) {
    asm volatile("ldmatrix.sync.aligned.m8n8.x4.shared.b16 {%0,%1,%2,%3}, [%4];"
                 : "=r"(r0), "=r"(r1), "=r"(r2), "=r"(r3) : "r"(a));
}
__device__ __forceinline__ void mmat(float* c, uint32_t a0, uint32_t a1, uint32_t a2,
                                     uint32_t a3, uint32_t b0, uint32_t b1) {
    asm volatile(
        "mma.sync.aligned.m16n8k8.row.col.f32.tf32.tf32.f32 "
        "{%0,%1,%2,%3},{%4,%5,%6,%7},{%8,%9},{%0,%1,%2,%3};"
        : "+f"(c[0]), "+f"(c[1]), "+f"(c[2]), "+f"(c[3])
        : "r"(a0), "r"(a1), "r"(a2), "r"(a3), "r"(b0), "r"(b1));
}

// ---------------- prep: K fp32 -> tf32 ----------------
__global__ void kcvt_kernel(const float* __restrict__ k) {
    int gid = blockIdx.x * 512 + threadIdx.x;
    float4 f = ((const float4*)k)[gid];
    ((uint4*)g_kt)[gid] = make_uint4(f2tf(f.x), f2tf(f.y), f2tf(f.z), f2tf(f.w));
}

// ---------------- prep: V fp32 -> tf32 transposed [bh][d][j] ----------------
__global__ void vtr_kernel(const float* __restrict__ v) {
    __shared__ uint32_t t[32][33];
    int bh = blockIdx.z, j0 = blockIdx.x * 32, d0 = blockIdx.y * 32;
    const float* src = v + ((size_t)bh * S_LEN + j0) * DHEAD + d0;
#pragma unroll
    for (int i = 0; i < 4; i++)
        t[threadIdx.y + i * 8][threadIdx.x] =
            f2tf(src[(threadIdx.y + i * 8) * DHEAD + threadIdx.x]);
    __syncthreads();
    uint32_t* dst = (uint32_t*)g_vt + ((size_t)bh * DHEAD + d0) * S_LEN + j0;
#pragma unroll
    for (int i = 0; i < 4; i++)
        dst[(threadIdx.y + i * 8) * S_LEN + threadIdx.x] = t[threadIdx.x][threadIdx.y + i * 8];
}

// ---------------- rnorm: rsqrt(sum_j omask[h,i,j]) ----------------
__global__ void rnorm_kernel(const float* __restrict__ omask) {
    int row = blockIdx.x;
    const float* p = omask + (size_t)row * S_LEN;
    float s = 0.f;
    for (int j = threadIdx.x * 4; j < S_LEN; j += 256 * 4) {
        float4 f = *(const float4*)(p + j);
        s += f.x + f.y + f.z + f.w;
    }
#pragma unroll
    for (int off = 16; off > 0; off >>= 1) s += __shfl_xor_sync(0xffffffffu, s, off);
    __shared__ float red[8];
    if ((threadIdx.x & 31) == 0) red[threadIdx.x >> 5] = s;
    __syncthreads();
    if (threadIdx.x == 0) {
        float t = 0.f;
#pragma unroll
        for (int i = 0; i < 8; i++) t += red[i];
        g_rnorm[row] = (t > 0.f) ? rsqrtf(t) : 0.f;
    }
}

__global__ __launch_bounds__(THREADS, 1)
void retention_mma_kernel(const float* __restrict__ q, const float* __restrict__ omask,
                          float* __restrict__ out) {
    extern __shared__ char smc[];
    const uint32_t su = smem_u32(smc);
    const int tid = threadIdx.x;
    const int wid = tid >> 5, lane = tid & 31;
    const int mw = wid >> 1, jw = wid & 1;  // 8 m-positions x 2 j-halves
    const int m0 = mw * 16;
    const int g = lane >> 2;
    const int c = lane & 3;

    const int it = blockIdx.x, h = blockIdx.y, b = blockIdx.z;
    const int i0 = it * BM;
    const size_t bh = (size_t)(b * HEADS + h);
    const float* qbase = q + (bh * S_LEN + i0) * DHEAD;
    const float* mbase = omask + ((size_t)h * S_LEN + i0) * S_LEN;
    const char* gkt = (const char*)g_kt + bh * (S_LEN * DHEAD * 4);
    const char* gvt = (const char*)g_vt + bh * (S_LEN * DHEAD * 4);

    // ---- issue K/V tile 0 via cp.async ----
#pragma unroll
    for (int i = 0; i < 4; i++) {
        int x = tid + i * THREADS;  // 0..2047
        int kr = x >> 5, kc = x & 31;
        cpa16(su + SM_K + kr * 512 + ((kc ^ (kr & 7)) << 4), gkt + (size_t)kr * 512 + kc * 16);
        int vr = x >> 4, vc = x & 15;
        cpa16(su + SM_V + vr * 256 + ((vc ^ (vr & 7)) << 4), gvt + (size_t)vr * 8192 + vc * 16);
    }
    asm volatile("cp.async.commit_group;" ::: "memory");

    // ---- Q tile [128x128] -> tf32 smem (swizzled 16B chunks) ----
#pragma unroll
    for (int i = 0; i < 8; i++) {
        int x = tid + i * THREADS;
        int r = x >> 5, ch = x & 31;
        float4 f = *(const float4*)(qbase + r * DHEAD + ch * 4);
        *(uint4*)(smc + SM_Q + r * 512 + ((ch ^ (r & 7)) << 4)) =
            make_uint4(f2tf(f.x), f2tf(f.y), f2tf(f.z), f2tf(f.w));
    }

    const float rn0 = g_rnorm[h * S_LEN + i0 + m0 + g];
    const float rn1 = g_rnorm[h * S_LEN + i0 + m0 + g + 8];

    float oacc[16][4];  // partial O over this warp's j-half, n8 tiles over d128
#pragma unroll
    for (int nt = 0; nt < 16; nt++)
#pragma unroll
        for (int e = 0; e < 4; e++) oacc[nt][e] = 0.f;

    // ldmatrix lane-address components
    const int qr = m0 + (lane & 7) + ((lane >> 3) & 1) * 8;  // A row for Q
    const int qcb = (lane >> 4);                              // A chunk sub-index
    const int krr = jw * 32 + (lane & 7);                     // K row base (add np*8)
    const int kcb = (lane >> 3);                              // K chunk sub (0..3)
    const int vrr = lane & 7;                                 // V row base (add n8*8)
    const int vcb = (lane >> 3);                              // V chunk sub (0..3)

    const int slo = (lane & ~3) | (c >> 1);
    const int shi = (lane & ~3) | ((c >> 1) + 2);
    const bool codd = (c & 1);

    for (int jt = 0; jt < NJT; jt++) {
        const int buf = jt & 1;
        __syncthreads();  // all reads of prev tiles done

        // ---- issue next K/V tiles into buf^1 ----
        if (jt + 1 < NJT) {
            const uint32_t sb = (buf ^ 1) * 32768;
            const size_t krb = (size_t)(jt + 1) * BN * 512;
            const size_t vcbyte = (size_t)(jt + 1) * 256;
#pragma unroll
            for (int i = 0; i < 4; i++) {
                int x = tid + i * THREADS;
                int kr = x >> 5, kc = x & 31;
                cpa16(su + SM_K + sb + kr * 512 + ((kc ^ (kr & 7)) << 4),
                      gkt + krb + (size_t)kr * 512 + kc * 16);
                int vr = x >> 4, vc = x & 15;
                cpa16(su + SM_V + sb + vr * 256 + ((vc ^ (vr & 7)) << 4),
                      gvt + (size_t)vr * 8192 + vcbyte + vc * 16);
            }
        }
        asm volatile("cp.async.commit_group;" ::: "memory");

        // ---- mask LDG (this warp's j32 half) ----
        const float* mp = mbase + (size_t)(m0 + g) * S_LEN + jt * BN + jw * 32 + c * 2;
        float2 mk0[4], mk1[4];
#pragma unroll
        for (int nt = 0; nt < 4; nt++) {
            mk0[nt] = *(const float2*)(mp + nt * 8);
            mk1[nt] = *(const float2*)(mp + 8 * S_LEN + nt * 8);
        }

        asm volatile("cp.async.wait_group 1;" ::: "memory");
        __syncthreads();  // current tiles visible

        const uint32_t khb = su + SM_K + buf * 32768;
        const uint32_t vhb = su + SM_V + buf * 32768;

        // ---- GEMM1: S[m16][j32] = Q @ K^T (tf32) ----
        float sacc[4][4];
#pragma unroll
        for (int nt = 0; nt < 4; nt++)
#pragma unroll
            for (int e = 0; e < 4; e++) sacc[nt][e] = 0.f;
#pragma unroll
        for (int ksp = 0; ksp < 8; ksp++) {  // kstep pairs (k16 per ksp)
            uint32_t a00, a01, a02, a03, a10, a11, a12, a13;
            ldmx4(a00, a01, a02, a03,
                  su + SM_Q + qr * 512 + (((4 * ksp + qcb) ^ (qr & 7)) << 4));
            ldmx4(a10, a11, a12, a13,
                  su + SM_Q + qr * 512 + (((4 * ksp + 2 + qcb) ^ (qr & 7)) << 4));
#pragma unroll
            for (int np = 0; np < 4; np++) {
                int krow = krr + np * 8;
                uint32_t b0, b1, b2, b3;
                ldmx4(b0, b1, b2, b3,
                      khb + krow * 512 + (((4 * ksp + kcb) ^ (krow & 7)) << 4));
                mmat(sacc[np], a00, a01, a02, a03, b0, b1);
                mmat(sacc[np], a10, a11, a12, a13, b2, b3);
            }
        }

        // ---- scale: sacc *= mask * rn ----
#pragma unroll
        for (int nt = 0; nt < 4; nt++) {
            sacc[nt][0] *= mk0[nt].x * rn0;
            sacc[nt][1] *= mk0[nt].y * rn0;
            sacc[nt][2] *= mk1[nt].x * rn1;
            sacc[nt][3] *= mk1[nt].y * rn1;
        }

        // ---- GEMM2: partial O += S @ V over this j-half ----
#pragma unroll
        for (int ktp = 0; ktp < 2; ktp++) {
            // build tf32 A-frags for kt = 2*ktp, 2*ktp+1 via lane shuffles
            uint32_t af[2][4];
#pragma unroll
            for (int kk = 0; kk < 2; kk++) {
                const float* s4 = sacc[2 * ktp + kk];
                float v0 = __shfl_sync(0xffffffffu, s4[0], slo);
                float v1 = __shfl_sync(0xffffffffu, s4[1], slo);
                float w0 = __shfl_sync(0xffffffffu, s4[0], shi);
                float w1 = __shfl_sync(0xffffffffu, s4[1], shi);
                float x0 = __shfl_sync(0xffffffffu, s4[2], slo);
                float x1 = __shfl_sync(0xffffffffu, s4[3], slo);
                float y0 = __shfl_sync(0xffffffffu, s4[2], shi);
                float y1 = __shfl_sync(0xffffffffu, s4[3], shi);
                af[kk][0] = f2tf(codd ? v1 : v0);
                af[kk][1] = f2tf(codd ? x1 : x0);
                af[kk][2] = f2tf(codd ? w1 : w0);
                af[kk][3] = f2tf(codd ? y1 : y0);
            }
#pragma unroll
            for (int n8 = 0; n8 < 16; n8++) {
                int vrow = vrr + n8 * 8;
                uint32_t b0, b1, b2, b3;
                // chunk index carries this warp's j-half offset (8*jw) — R12 fix
                ldmx4(b0, b1, b2, b3,
                      vhb + vrow * 256 + (((8 * jw + 4 * ktp + vcb) ^ (vrow & 7)) << 4));
                mmat(oacc[n8], af[0][0], af[0][1], af[0][2], af[0][3], b0, b1);
                mmat(oacc[n8], af[1][0], af[1][1], af[1][2], af[1][3], b2, b3);
            }
        }
    }

    // ---- cross-warp O reduction (jw=1 -> smem, jw=0 adds) ----
    float* rbase = (float*)smc + mw * 16 * RED_STRIDE;
    __syncthreads();
    if (jw == 1) {
        float* r0 = rbase + g * RED_STRIDE + c * 2;
        float* r1 = rbase + (g + 8) * RED_STRIDE + c * 2;
#pragma unroll
        for (int nt = 0; nt < 16; nt++) {
            *(float2*)(r0 + nt * 8) = make_float2(oacc[nt][0], oacc[nt][1]);
            *(float2*)(r1 + nt * 8) = make_float2(oacc[nt][2], oacc[nt][3]);
        }
    }
    __syncthreads();
    if (jw == 0) {
        const float* r0 = rbase + g * RED_STRIDE + c * 2;
        const float* r1 = rbase + (g + 8) * RED_STRIDE + c * 2;
#pragma unroll
        for (int nt = 0; nt < 16; nt++) {
            float2 a = *(const float2*)(r0 + nt * 8);
            float2 b2 = *(const float2*)(r1 + nt * 8);
            oacc[nt][0] += a.x;
            oacc[nt][1] += a.y;
            oacc[nt][2] += b2.x;
            oacc[nt][3] += b2.y;
        }

        // ---- RMSNorm + store ----
        float p0 = 0.f, p1 = 0.f;
#pragma unroll
        for (int nt = 0; nt < 16; nt++) {
            p0 += oacc[nt][0] * oacc[nt][0] + oacc[nt][1] * oacc[nt][1];
            p1 += oacc[nt][2] * oacc[nt][2] + oacc[nt][3] * oacc[nt][3];
        }
        p0 += __shfl_xor_sync(0xffffffffu, p0, 1);
        p0 += __shfl_xor_sync(0xffffffffu, p0, 2);
        p1 += __shfl_xor_sync(0xffffffffu, p1, 1);
        p1 += __shfl_xor_sync(0xffffffffu, p1, 2);
        float sc0 = rsqrtf(p0 * (1.f / 128.f) + 1e-6f);
        float sc1 = rsqrtf(p1 * (1.f / 128.f) + 1e-6f);
        float* o0 = out + (bh * S_LEN + i0 + m0 + g) * DHEAD + c * 2;
        float* o1 = o0 + 8 * DHEAD;
#pragma unroll
        for (int nt = 0; nt < 16; nt++) {
            *(float2*)(o0 + nt * 8) = make_float2(oacc[nt][0] * sc0, oacc[nt][1] * sc0);
            *(float2*)(o1 + nt * 8) = make_float2(oacc[nt][2] * sc1, oacc[nt][3] * sc1);
        }
    }
}

extern "C" void kernel_launch(void* const* d_in, const int* in_sizes, int n_in,
                              void* d_out, int out_size) {
    const float* q = (const float*)d_in[0];
    const float* k = (const float*)d_in[1];
    const float* v = (const float*)d_in[2];
    const float* omask = (const float*)d_in[3];
    float* out = (float*)d_out;

    cudaFuncSetAttribute(retention_mma_kernel, cudaFuncAttributeMaxDynamicSharedMemorySize,
                         SMEM_TOTAL);

    kcvt_kernel<<<NROWS * DHEAD / (512 * 4), 512>>>(k);
    vtr_kernel<<<dim3(S_LEN / 32, DHEAD / 32, BATCH * HEADS), dim3(32, 8)>>>(v);
    rnorm_kernel<<<HEADS * S_LEN, 256>>>(omask);
    retention_mma_kernel<<<dim3(S_LEN / BM, HEADS, BATCH), THREADS, SMEM_TOTAL>>>(
        q, omask, out);
}